// round 16
// baseline (speedup 1.0000x reference)
#include <cuda_runtime.h>
#include <cuda_fp16.h>
#include <cstdint>
#include <cstddef>

#define N_NODES 50000
#define HD      128
#define NB      8
#define NR      16
#define NE      640000
#define TILE_M  128
#define MAX_TILES (NE / TILE_M + NR)          // 5016
#define HB_EDGES  4096
#define NHB ((NE + HB_EDGES - 1) / HB_EDGES)  // 157

#define TILE_BYTES 32768                      // 128 x 128 fp16, swizzled image
#define CSTRIDE    544                        // C-staging row stride (bytes)
#define CSTAGE_BYTES (128 * CSTRIDE)          // 69632

// ---------------- scratch (device globals; no allocs allowed) ----------------
__device__ __half g_h_f16[(size_t)N_NODES * HD];         // 12.8 MB
__device__ unsigned char g_w_pk1[(size_t)NR * TILE_BYTES];  // layer-1 W, swizzled
__device__ unsigned char g_w_pk2[(size_t)NR * TILE_BYTES];  // layer-2 W, swizzled
__device__ float g_h1[(size_t)N_NODES * HD];             // layer-1 output
__device__ int  g_sorted[NE];
__device__ int  g_hist[NR];
__device__ int  g_cursor[NR];
__device__ int4 g_tiles[MAX_TILES];                      // {rel, start, cnt, 0}
__device__ int  g_ntiles;

// ---------------------------------------------------------------------------
__device__ __forceinline__ void cp_async16_s(uint32_t s, const void* g)
{
    asm volatile("cp.async.ca.shared.global [%0], [%1], 16;\n" :: "r"(s), "l"(g));
}

// Blocked-atom SW128 byte offset for element (row, k) of a [128 x 128] b16
// K-major tile: atom = 8 rows x 64 elems (1024 B); atoms tile M first (16),
// then K (2). XOR source is purely row&7 -> ldmatrix conflict-free.
__device__ __forceinline__ uint32_t toff(int row, int k)
{
    uint32_t atom = (uint32_t)((row >> 3) + (k >> 6) * 16);
    uint32_t sw   = ((uint32_t)(k & 63) * 2) ^ (((uint32_t)row & 7) << 4);
    return atom * 1024 + ((uint32_t)row & 7) * 128 + sw;
}

#define LDSM_X4(r0, r1, r2, r3, addr)                                        \
    asm volatile("ldmatrix.sync.aligned.m8n8.x4.shared.b16 {%0,%1,%2,%3}, [%4];" \
                 : "=r"(r0), "=r"(r1), "=r"(r2), "=r"(r3) : "r"(addr))

__device__ __forceinline__ void mma16816(float c[4],
                                         uint32_t a0, uint32_t a1, uint32_t a2, uint32_t a3,
                                         uint32_t b0, uint32_t b1)
{
    asm volatile(
        "mma.sync.aligned.m16n8k16.row.col.f32.f16.f16.f32 "
        "{%0,%1,%2,%3}, {%4,%5,%6,%7}, {%8,%9}, {%0,%1,%2,%3};\n"
        : "+f"(c[0]), "+f"(c[1]), "+f"(c[2]), "+f"(c[3])
        : "r"(a0), "r"(a1), "r"(a2), "r"(a3), "r"(b0), "r"(b1));
}

// ---------------- bucketing: counting sort of edges by relation -------------
__global__ void k_zero_hist()
{
    if (threadIdx.x < NR) g_hist[threadIdx.x] = 0;
}

__global__ __launch_bounds__(256) void k_hist(const int* __restrict__ et)
{
    __shared__ int sh[NR];
    if (threadIdx.x < NR) sh[threadIdx.x] = 0;
    __syncthreads();
    int base = blockIdx.x * HB_EDGES;
    int end  = min(base + HB_EDGES, NE);
    for (int i = base + threadIdx.x; i < end; i += 256)
        atomicAdd(&sh[__ldg(&et[i])], 1);
    __syncthreads();
    if (threadIdx.x < NR) atomicAdd(&g_hist[threadIdx.x], sh[threadIdx.x]);
}

__global__ __launch_bounds__(256) void k_scan_tiles()
{
    __shared__ int off[NR + 1], tb[NR + 1];
    if (threadIdx.x == 0) {
        int acc = 0, t = 0;
        for (int r = 0; r < NR; r++) {
            off[r] = acc; tb[r] = t;
            g_cursor[r] = acc;
            int c = g_hist[r];
            acc += c;
            t += (c + TILE_M - 1) / TILE_M;
        }
        off[NR] = acc; tb[NR] = t;
        g_ntiles = t;
    }
    __syncthreads();
    int nt = tb[NR];
    for (int idx = threadIdx.x; idx < nt; idx += 256) {
        int r = 0;
        while (tb[r + 1] <= idx) r++;
        int local = idx - tb[r];
        int start = off[r] + local * TILE_M;
        int cnt   = min(TILE_M, off[r + 1] - start);
        g_tiles[idx] = make_int4(r, start, cnt, 0);
    }
}

__global__ __launch_bounds__(256) void k_place(const int* __restrict__ et)
{
    __shared__ int sh[NR], sbase[NR];
    if (threadIdx.x < NR) sh[threadIdx.x] = 0;
    __syncthreads();
    int base = blockIdx.x * HB_EDGES;
    int end  = min(base + HB_EDGES, NE);
    for (int i = base + threadIdx.x; i < end; i += 256)
        atomicAdd(&sh[__ldg(&et[i])], 1);
    __syncthreads();
    if (threadIdx.x < NR) {
        sbase[threadIdx.x] = atomicAdd(&g_cursor[threadIdx.x], sh[threadIdx.x]);
        sh[threadIdx.x] = 0;
    }
    __syncthreads();
    for (int i = base + threadIdx.x; i < end; i += 256) {
        int r = __ldg(&et[i]);
        int p = sbase[r] + atomicAdd(&sh[r], 1);
        g_sorted[p] = i;
    }
}

// ---- W[r] = coef[r]·basis for BOTH layers, packed fp16 swizzled [o][k] -----
__global__ __launch_bounds__(256) void k_fold_w2(
    const float* __restrict__ basis1, const float* __restrict__ coef1,
    const float* __restrict__ basis2, const float* __restrict__ coef2)
{
    int blk = blockIdx.x;
    int r   = blk & (NR - 1);
    const float* basis = (blk < NR) ? basis1 : basis2;
    const float* coef  = (blk < NR) ? coef1  : coef2;
    unsigned char* wp  = ((blk < NR) ? g_w_pk1 : g_w_pk2) + (size_t)r * TILE_BYTES;

    __shared__ float cf[NB];
    if (threadIdx.x < NB) cf[threadIdx.x] = coef[r * NB + threadIdx.x];
    __syncthreads();
    for (int e = threadIdx.x; e < HD * HD; e += 256) {
        int k = e >> 7, o = e & 127;
        float acc = 0.f;
#pragma unroll
        for (int b = 0; b < NB; b++)
            acc = fmaf(cf[b], basis[((size_t)b * HD + k) * HD + o], acc);
        *(__half*)(wp + toff(o, k)) = __float2half_rn(acc);
    }
}

// ---- fp16 node features (optional ReLU) + init dst with bias ---------------
template <bool RELU>
__global__ __launch_bounds__(256) void k_split_init(const float* __restrict__ x,
                                                    const float* __restrict__ bias,
                                                    float* __restrict__ dstbuf)
{
    int idx = blockIdx.x * 256 + threadIdx.x;
    if (idx < N_NODES * HD) {
        float v = x[idx];
        if (RELU) v = fmaxf(v, 0.f);
        g_h_f16[idx] = __float2half_rn(v);
        dstbuf[idx] = bias[idx & (HD - 1)];
    }
}

// ---------------------------------------------------------------------------
// Fused gather-GEMM-scatter. One block = one 128-edge tile of one relation.
//   C[128x128] = fp16(h)[src_tile] @ fp16(W[rel])^T
//   epilogue: stage C in SMEM (tiles dead after K-loop), then warp-per-row
//   coalesced red.global.add.v4 (one 512B burst per dst row).
// 256 threads (8 warps 2x4), warp tile 64x32, SW128 blocked-atom tiles +
// ldmatrix.x4, 2-group cp.async. 2 CTAs/SM.
// ---------------------------------------------------------------------------
__global__ __launch_bounds__(256, 2) void k_edge_gemm(
    const int* __restrict__ src, const int* __restrict__ dst,
    const float* __restrict__ norm, const unsigned char* __restrict__ w_pk,
    float* __restrict__ out)
{
    if ((int)blockIdx.x >= g_ntiles) return;
    int4 tl  = g_tiles[blockIdx.x];
    int  rel = tl.x, start = tl.y, cnt = tl.z;

    extern __shared__ char smem[];
    uint32_t base = (uint32_t)__cvta_generic_to_shared(smem);
    int*   srcv  = (int*)smem;
    int*   dstv  = (int*)(smem + 512);
    float* normv = (float*)(smem + 1024);
    uint32_t tiles_a = (base + 2048 + 1023) & ~1023u;   // 1024-aligned
    uint32_t sa_t = tiles_a;
    uint32_t sw_t = tiles_a + TILE_BYTES;
    char*    cst  = smem + (tiles_a - base);            // C staging (reuses tiles)

    const int tid  = threadIdx.x;
    const int lane = tid & 31;

    if (tid < 128) {
        if (tid < cnt) {
            int eid = g_sorted[start + tid];
            srcv[tid]  = __ldg(&src[eid]);
            dstv[tid]  = __ldg(&dst[eid]);
            normv[tid] = __ldg(&norm[eid]);
        } else {
            srcv[tid] = 0; dstv[tid] = -1; normv[tid] = 0.f;
        }
    }
    __syncthreads();

    const int arow = tid >> 1, apart = tid & 1;          // A: 2 threads/row
    const __half* gA = g_h_f16 + (size_t)srcv[arow] * HD;

    // ---- group 0: W tile (straight copy of swizzled image) + A cols [0,64)
    {
        const unsigned char* wp = w_pk + (size_t)rel * TILE_BYTES;
#pragma unroll
        for (int i = 0; i < 8; i++) {
            int off = tid * 16 + i * 4096;
            cp_async16_s(sw_t + off, wp + off);
        }
#pragma unroll
        for (int c = 0; c < 4; c++) {
            int k = apart * 32 + c * 8;                  // [0,64) across 2 threads
            cp_async16_s(sa_t + toff(arow, k), gA + k);
        }
    }
    asm volatile("cp.async.commit_group;\n" ::: "memory");
    // ---- group 1: A cols [64,128)
    {
#pragma unroll
        for (int c = 0; c < 4; c++) {
            int k = 64 + apart * 32 + c * 8;
            cp_async16_s(sa_t + toff(arow, k), gA + k);
        }
    }
    asm volatile("cp.async.commit_group;\n" ::: "memory");

    const int warp = tid >> 5;
    const int wm = warp >> 2, wn = warp & 3;     // warp tile: rows wm*64, cols wn*32
    const int mid = lane >> 3, rin = lane & 7;   // ldmatrix group / row-in-group

    float c[4][4][4];
#pragma unroll
    for (int mt = 0; mt < 4; mt++)
#pragma unroll
        for (int nt = 0; nt < 4; nt++)
#pragma unroll
            for (int q = 0; q < 4; q++) c[mt][nt][q] = 0.f;

    asm volatile("cp.async.wait_group 1;\n" ::: "memory");   // group 0 done
    __syncthreads();

#pragma unroll
    for (int ks = 0; ks < HD; ks += 16) {
        if (ks == 64) {
            asm volatile("cp.async.wait_group 0;\n" ::: "memory");
            __syncthreads();
        }
        // A fragments: groups (rows+0,k0)(rows+8,k0)(rows+0,k8)(rows+8,k8)
        uint32_t aa[4][4];
        int ka = ks + ((mid >> 1) << 3);
        int ra = ((mid & 1) << 3) + rin;
#pragma unroll
        for (int mt = 0; mt < 4; mt++) {
            uint32_t ro = toff(wm * 64 + mt * 16 + ra, ka);
            LDSM_X4(aa[mt][0], aa[mt][1], aa[mt][2], aa[mt][3], sa_t + ro);
        }
        // B fragments: groups (nt,k0)(nt,k8)(nt+1,k0)(nt+1,k8)
        uint32_t bb[2][4];
        int kb = ks + ((mid & 1) << 3);
#pragma unroll
        for (int p = 0; p < 2; p++) {
            int nc = wn * 32 + p * 16 + ((mid >> 1) << 3) + rin;
            LDSM_X4(bb[p][0], bb[p][1], bb[p][2], bb[p][3], sw_t + toff(nc, kb));
        }
#pragma unroll
        for (int mt = 0; mt < 4; mt++)
#pragma unroll
            for (int nt = 0; nt < 4; nt++) {
                uint32_t b0 = bb[nt >> 1][(nt & 1) * 2];
                uint32_t b1 = bb[nt >> 1][(nt & 1) * 2 + 1];
                mma16816(c[mt][nt], aa[mt][0], aa[mt][1], aa[mt][2], aa[mt][3], b0, b1);
            }
    }

    // ---- epilogue: stage C into SMEM (tiles dead), then coalesced reds.
    __syncthreads();   // all LDSM reads of tiles complete before overwrite
    {
        const int gq = lane >> 2, tq = lane & 3;
#pragma unroll
        for (int mt = 0; mt < 4; mt++) {
            int row0 = wm * 64 + mt * 16 + gq;
#pragma unroll
            for (int nt = 0; nt < 4; nt++) {
                int col = wn * 32 + nt * 8 + tq * 2;
                // stride 544B/row: STS.64 bank-conflict-free (136 % 32 = 8 words)
                *(float2*)(cst + row0 * CSTRIDE + col * 4) =
                    make_float2(c[mt][nt][0], c[mt][nt][1]);
                *(float2*)(cst + (row0 + 8) * CSTRIDE + col * 4) =
                    make_float2(c[mt][nt][2], c[mt][nt][3]);
            }
        }
    }
    __syncthreads();
    {
        // warp w owns rows w*16 .. w*16+15; per row: one coalesced 512B red burst
#pragma unroll
        for (int i = 0; i < 16; i++) {
            int row = warp * 16 + i;
            int   d  = dstv[row];
            if (d < 0) continue;
            float nm = normv[row];
            float4 v = *(const float4*)(cst + row * CSTRIDE + lane * 16);
            float* p = out + (size_t)d * HD + lane * 4;
            asm volatile(
                "red.global.add.v4.f32 [%0], {%1,%2,%3,%4};"
                :: "l"(p), "f"(v.x * nm), "f"(v.y * nm),
                   "f"(v.z * nm), "f"(v.w * nm)
                : "memory");
        }
    }
}

// ---------------------------------------------------------------------------
// kernel_launch
// Inputs: 0:h 1:norm 2:src 3:dst 4:etype 5:V1 6:coef1 7:bias1 8:V2 9:coef2 10:bias2
// ---------------------------------------------------------------------------
extern "C" void kernel_launch(void* const* d_in, const int* in_sizes, int n_in,
                              void* d_out, int out_size)
{
    const float* h     = (const float*)d_in[0];
    const float* norm  = (const float*)d_in[1];
    const int*   src   = (const int*)d_in[2];
    const int*   dst   = (const int*)d_in[3];
    const int*   etype = (const int*)d_in[4];
    const float* V1    = (const float*)d_in[5];
    const float* coef1 = (const float*)d_in[6];
    const float* bias1 = (const float*)d_in[7];
    const float* V2    = (const float*)d_in[8];
    const float* coef2 = (const float*)d_in[9];
    const float* bias2 = (const float*)d_in[10];
    float*       out   = (float*)d_out;

    float* h1;  cudaGetSymbolAddress((void**)&h1, g_h1);
    unsigned char *w1, *w2;
    cudaGetSymbolAddress((void**)&w1, g_w_pk1);
    cudaGetSymbolAddress((void**)&w2, g_w_pk2);

    static int smem_set = 0;
    const int GEMM_SMEM = 2048 + 1024 + CSTAGE_BYTES;   // ~71 KB -> 2 CTAs/SM
    if (!smem_set) {
        cudaFuncSetAttribute(k_edge_gemm,
                             cudaFuncAttributeMaxDynamicSharedMemorySize, GEMM_SMEM);
        smem_set = 1;
    }

    int nh_elems  = N_NODES * HD;
    int elem_grid = (nh_elems + 255) / 256;

    // ---- prep: bucketing (shared by both layers) + both W folds
    k_zero_hist<<<1, 32>>>();
    k_hist<<<NHB, 256>>>(etype);
    k_scan_tiles<<<1, 256>>>();
    k_place<<<NHB, 256>>>(etype);
    k_fold_w2<<<2 * NR, 256>>>(V1, coef1, V2, coef2);

    // ---- Layer 1
    k_split_init<false><<<elem_grid, 256>>>(h, bias1, h1);
    k_edge_gemm<<<MAX_TILES, 256, GEMM_SMEM>>>(src, dst, norm, w1, h1);

    // ---- Layer 2
    k_split_init<true><<<elem_grid, 256>>>(h1, bias2, out);
    k_edge_gemm<<<MAX_TILES, 256, GEMM_SMEM>>>(src, dst, norm, w2, out);
}

// round 17
// speedup vs baseline: 1.4134x; 1.4134x over previous
#include <cuda_runtime.h>
#include <cuda_fp16.h>
#include <cstdint>
#include <cstddef>

#define N_NODES 50000
#define HD      128
#define NB      8
#define NR      16
#define NE      640000
#define TILE_M  128
#define MAX_TILES (NE / TILE_M + NR)          // 5016
#define HB_EDGES  4096
#define NHB ((NE + HB_EDGES - 1) / HB_EDGES)  // 157

#define TILE_BYTES 32768                      // 128 x 128 fp16, swizzled image

// ---------------- scratch (device globals; no allocs allowed) ----------------
__device__ __half g_h_f16[(size_t)N_NODES * HD];         // 12.8 MB
__device__ unsigned char g_w_pk1[(size_t)NR * TILE_BYTES];  // layer-1 W, swizzled
__device__ unsigned char g_w_pk2[(size_t)NR * TILE_BYTES];  // layer-2 W, swizzled
__device__ float g_h1[(size_t)N_NODES * HD];             // layer-1 output
__device__ int4 g_meta[NE];                              // sorted {src,dst,norm,0}
__device__ int  g_hist[NR];
__device__ int  g_cursor[NR];
__device__ int4 g_tiles[MAX_TILES];                      // {rel, start, cnt, 0}
__device__ int  g_ntiles;

// ---------------------------------------------------------------------------
__device__ __forceinline__ void cp_async16_s(uint32_t s, const void* g)
{
    asm volatile("cp.async.ca.shared.global [%0], [%1], 16;\n" :: "r"(s), "l"(g));
}

// Blocked-atom SW128 byte offset for element (row, k) of a [128 x 128] b16
// K-major tile: atom = 8 rows x 64 elems (1024 B); atoms tile M first (16),
// then K (2). XOR source is purely row&7 -> ldmatrix conflict-free.
__device__ __forceinline__ uint32_t toff(int row, int k)
{
    uint32_t atom = (uint32_t)((row >> 3) + (k >> 6) * 16);
    uint32_t sw   = ((uint32_t)(k & 63) * 2) ^ (((uint32_t)row & 7) << 4);
    return atom * 1024 + ((uint32_t)row & 7) * 128 + sw;
}

#define LDSM_X4(r0, r1, r2, r3, addr)                                        \
    asm volatile("ldmatrix.sync.aligned.m8n8.x4.shared.b16 {%0,%1,%2,%3}, [%4];" \
                 : "=r"(r0), "=r"(r1), "=r"(r2), "=r"(r3) : "r"(addr))

__device__ __forceinline__ void mma16816(float c[4],
                                         uint32_t a0, uint32_t a1, uint32_t a2, uint32_t a3,
                                         uint32_t b0, uint32_t b1)
{
    asm volatile(
        "mma.sync.aligned.m16n8k16.row.col.f32.f16.f16.f32 "
        "{%0,%1,%2,%3}, {%4,%5,%6,%7}, {%8,%9}, {%0,%1,%2,%3};\n"
        : "+f"(c[0]), "+f"(c[1]), "+f"(c[2]), "+f"(c[3])
        : "r"(a0), "r"(a1), "r"(a2), "r"(a3), "r"(b0), "r"(b1));
}

// ---------------- bucketing: counting sort of edges by relation -------------
__global__ void k_zero_hist()
{
    if (threadIdx.x < NR) g_hist[threadIdx.x] = 0;
}

__global__ __launch_bounds__(256) void k_hist(const int* __restrict__ et)
{
    __shared__ int sh[NR];
    if (threadIdx.x < NR) sh[threadIdx.x] = 0;
    __syncthreads();
    int base = blockIdx.x * HB_EDGES;
    int end  = min(base + HB_EDGES, NE);
    for (int i = base + threadIdx.x; i < end; i += 256)
        atomicAdd(&sh[__ldg(&et[i])], 1);
    __syncthreads();
    if (threadIdx.x < NR) atomicAdd(&g_hist[threadIdx.x], sh[threadIdx.x]);
}

__global__ __launch_bounds__(256) void k_scan_tiles()
{
    __shared__ int off[NR + 1], tb[NR + 1];
    if (threadIdx.x == 0) {
        int acc = 0, t = 0;
        for (int r = 0; r < NR; r++) {
            off[r] = acc; tb[r] = t;
            g_cursor[r] = acc;
            int c = g_hist[r];
            acc += c;
            t += (c + TILE_M - 1) / TILE_M;
        }
        off[NR] = acc; tb[NR] = t;
        g_ntiles = t;
    }
    __syncthreads();
    int nt = tb[NR];
    for (int idx = threadIdx.x; idx < nt; idx += 256) {
        int r = 0;
        while (tb[r + 1] <= idx) r++;
        int local = idx - tb[r];
        int start = off[r] + local * TILE_M;
        int cnt   = min(TILE_M, off[r + 1] - start);
        g_tiles[idx] = make_int4(r, start, cnt, 0);
    }
}

// place + pack: write sorted meta {src,dst,norm} directly (no g_sorted hop)
__global__ __launch_bounds__(256) void k_place(const int* __restrict__ et,
                                               const int* __restrict__ src,
                                               const int* __restrict__ dst,
                                               const float* __restrict__ norm)
{
    __shared__ int sh[NR], sbase[NR];
    if (threadIdx.x < NR) sh[threadIdx.x] = 0;
    __syncthreads();
    int base = blockIdx.x * HB_EDGES;
    int end  = min(base + HB_EDGES, NE);
    for (int i = base + threadIdx.x; i < end; i += 256)
        atomicAdd(&sh[__ldg(&et[i])], 1);
    __syncthreads();
    if (threadIdx.x < NR) {
        sbase[threadIdx.x] = atomicAdd(&g_cursor[threadIdx.x], sh[threadIdx.x]);
        sh[threadIdx.x] = 0;
    }
    __syncthreads();
    for (int i = base + threadIdx.x; i < end; i += 256) {
        int r = __ldg(&et[i]);
        int p = sbase[r] + atomicAdd(&sh[r], 1);
        g_meta[p] = make_int4(__ldg(&src[i]), __ldg(&dst[i]),
                              __float_as_int(__ldg(&norm[i])), 0);
    }
}

// ---- W[r] = coef[r]·basis for BOTH layers, packed fp16 swizzled [o][k] -----
__global__ __launch_bounds__(256) void k_fold_w2(
    const float* __restrict__ basis1, const float* __restrict__ coef1,
    const float* __restrict__ basis2, const float* __restrict__ coef2)
{
    int blk = blockIdx.x;
    int r   = blk & (NR - 1);
    const float* basis = (blk < NR) ? basis1 : basis2;
    const float* coef  = (blk < NR) ? coef1  : coef2;
    unsigned char* wp  = ((blk < NR) ? g_w_pk1 : g_w_pk2) + (size_t)r * TILE_BYTES;

    __shared__ float cf[NB];
    if (threadIdx.x < NB) cf[threadIdx.x] = coef[r * NB + threadIdx.x];
    __syncthreads();
    for (int e = threadIdx.x; e < HD * HD; e += 256) {
        int k = e >> 7, o = e & 127;
        float acc = 0.f;
#pragma unroll
        for (int b = 0; b < NB; b++)
            acc = fmaf(cf[b], basis[((size_t)b * HD + k) * HD + o], acc);
        *(__half*)(wp + toff(o, k)) = __float2half_rn(acc);
    }
}

// ---- fp16 node features (optional ReLU) + init dst with bias ---------------
template <bool RELU>
__global__ __launch_bounds__(256) void k_split_init(const float* __restrict__ x,
                                                    const float* __restrict__ bias,
                                                    float* __restrict__ dstbuf)
{
    int idx = blockIdx.x * 256 + threadIdx.x;
    if (idx < N_NODES * HD) {
        float v = x[idx];
        if (RELU) v = fmaxf(v, 0.f);
        g_h_f16[idx] = __float2half_rn(v);
        dstbuf[idx] = bias[idx & (HD - 1)];
    }
}

// ---------------------------------------------------------------------------
// Fused gather-GEMM-scatter. One block = one 128-edge tile of one relation.
//   C[128x128] = fp16(h)[src_tile] @ fp16(W[rel])^T
//   red.global.add.v4.f32(out[dst_i][:], C[i][:] * norm_i)
// 256 threads (8 warps 2x4), warp tile 64x32, SW128 blocked-atom tiles +
// ldmatrix.x4. Loads in 2 commit groups split at k=64 (W half + A half each)
// so the first K-half computes while the second half lands. 2 CTAs/SM.
// ---------------------------------------------------------------------------
__global__ __launch_bounds__(256, 2) void k_edge_gemm(
    const unsigned char* __restrict__ w_pk, float* __restrict__ out)
{
    if ((int)blockIdx.x >= g_ntiles) return;
    int4 tl  = g_tiles[blockIdx.x];
    int  rel = tl.x, start = tl.y, cnt = tl.z;

    extern __shared__ char smem[];
    uint32_t base = (uint32_t)__cvta_generic_to_shared(smem);
    int*   srcv  = (int*)smem;
    int*   dstv  = (int*)(smem + 512);
    float* normv = (float*)(smem + 1024);
    uint32_t tiles_a = (base + 2048 + 1023) & ~1023u;   // 1024-aligned
    uint32_t sa_t = tiles_a;
    uint32_t sw_t = tiles_a + TILE_BYTES;

    const int tid  = threadIdx.x;
    const int lane = tid & 31;

    if (tid < 128) {
        if (tid < cnt) {
            int4 m = __ldg(&g_meta[start + tid]);       // one coalesced burst
            srcv[tid]  = m.x;
            dstv[tid]  = m.y;
            normv[tid] = __int_as_float(m.z);
        } else {
            srcv[tid] = 0; dstv[tid] = -1; normv[tid] = 0.f;
        }
    }
    __syncthreads();

    const int arow = tid >> 1, apart = tid & 1;          // A: 2 threads/row
    const __half* gA = g_h_f16 + (size_t)srcv[arow] * HD;
    const unsigned char* wp = w_pk + (size_t)rel * TILE_BYTES;

    // ---- group 0: W[k<64] (first 16 KB of swizzled image) + A cols [0,64)
    {
#pragma unroll
        for (int i = 0; i < 4; i++) {
            int off = tid * 16 + i * 4096;
            cp_async16_s(sw_t + off, wp + off);
        }
#pragma unroll
        for (int c = 0; c < 4; c++) {
            int k = apart * 32 + c * 8;                  // [0,64) across 2 threads
            cp_async16_s(sa_t + toff(arow, k), gA + k);
        }
    }
    asm volatile("cp.async.commit_group;\n" ::: "memory");
    // ---- group 1: W[k>=64] + A cols [64,128)
    {
#pragma unroll
        for (int i = 4; i < 8; i++) {
            int off = tid * 16 + i * 4096;
            cp_async16_s(sw_t + off, wp + off);
        }
#pragma unroll
        for (int c = 0; c < 4; c++) {
            int k = 64 + apart * 32 + c * 8;
            cp_async16_s(sa_t + toff(arow, k), gA + k);
        }
    }
    asm volatile("cp.async.commit_group;\n" ::: "memory");

    const int warp = tid >> 5;
    const int wm = warp >> 2, wn = warp & 3;     // warp tile: rows wm*64, cols wn*32
    const int mid = lane >> 3, rin = lane & 7;   // ldmatrix group / row-in-group

    float c[4][4][4];
#pragma unroll
    for (int mt = 0; mt < 4; mt++)
#pragma unroll
        for (int nt = 0; nt < 4; nt++)
#pragma unroll
            for (int q = 0; q < 4; q++) c[mt][nt][q] = 0.f;

    asm volatile("cp.async.wait_group 1;\n" ::: "memory");   // group 0 done
    __syncthreads();

#pragma unroll
    for (int ks = 0; ks < HD; ks += 16) {
        if (ks == 64) {
            asm volatile("cp.async.wait_group 0;\n" ::: "memory");
            __syncthreads();
        }
        // A fragments: groups (rows+0,k0)(rows+8,k0)(rows+0,k8)(rows+8,k8)
        uint32_t aa[4][4];
        int ka = ks + ((mid >> 1) << 3);
        int ra = ((mid & 1) << 3) + rin;
#pragma unroll
        for (int mt = 0; mt < 4; mt++) {
            uint32_t ro = toff(wm * 64 + mt * 16 + ra, ka);
            LDSM_X4(aa[mt][0], aa[mt][1], aa[mt][2], aa[mt][3], sa_t + ro);
        }
        // B fragments: groups (nt,k0)(nt,k8)(nt+1,k0)(nt+1,k8)
        uint32_t bb[2][4];
        int kb = ks + ((mid & 1) << 3);
#pragma unroll
        for (int p = 0; p < 2; p++) {
            int nc = wn * 32 + p * 16 + ((mid >> 1) << 3) + rin;
            LDSM_X4(bb[p][0], bb[p][1], bb[p][2], bb[p][3], sw_t + toff(nc, kb));
        }
#pragma unroll
        for (int mt = 0; mt < 4; mt++)
#pragma unroll
            for (int nt = 0; nt < 4; nt++) {
                uint32_t b0 = bb[nt >> 1][(nt & 1) * 2];
                uint32_t b1 = bb[nt >> 1][(nt & 1) * 2 + 1];
                mma16816(c[mt][nt], aa[mt][0], aa[mt][1], aa[mt][2], aa[mt][3], b0, b1);
            }
    }

    // ---- scatter epilogue with vectorized reductions.
    // Fragment: thread (gq, t) holds rows (row0, row0+8), cols 2t..2t+1 per nt.
    // Pair-transpose via shfl_xor(1): even lanes assemble 4 consecutive row0
    // cols, odd lanes 4 consecutive row1 cols -> one red.global.add.v4.f32.
    {
        const int gq = lane >> 2, t = lane & 3;
        const bool even = (t & 1) == 0;
#pragma unroll
        for (int mt = 0; mt < 4; mt++) {
            int row0 = wm * 64 + mt * 16 + gq;
            int rown = even ? row0 : row0 + 8;
            int   d  = dstv[rown];
            float nm = normv[rown];
#pragma unroll
            for (int nt = 0; nt < 4; nt++) {
                float e0 = __shfl_xor_sync(0xFFFFFFFFu, c[mt][nt][0], 1);
                float e1 = __shfl_xor_sync(0xFFFFFFFFu, c[mt][nt][1], 1);
                float e2 = __shfl_xor_sync(0xFFFFFFFFu, c[mt][nt][2], 1);
                float e3 = __shfl_xor_sync(0xFFFFFFFFu, c[mt][nt][3], 1);
                float v0, v1, v2, v3;
                int col;
                if (even) {  // row0: own cols 2t,2t+1 + partner cols 2t+2,2t+3
                    v0 = c[mt][nt][0]; v1 = c[mt][nt][1]; v2 = e0; v3 = e1;
                    col = wn * 32 + nt * 8 + t * 2;
                } else {     // row1: partner cols 2t-2,2t-1 + own cols 2t,2t+1
                    v0 = e2; v1 = e3; v2 = c[mt][nt][2]; v3 = c[mt][nt][3];
                    col = wn * 32 + nt * 8 + (t - 1) * 2;
                }
                if (d >= 0) {
                    float* p = out + (size_t)d * HD + col;
                    asm volatile(
                        "red.global.add.v4.f32 [%0], {%1,%2,%3,%4};"
                        :: "l"(p), "f"(v0 * nm), "f"(v1 * nm),
                           "f"(v2 * nm), "f"(v3 * nm)
                        : "memory");
                }
            }
        }
    }
}

// ---------------------------------------------------------------------------
// kernel_launch
// Inputs: 0:h 1:norm 2:src 3:dst 4:etype 5:V1 6:coef1 7:bias1 8:V2 9:coef2 10:bias2
// ---------------------------------------------------------------------------
extern "C" void kernel_launch(void* const* d_in, const int* in_sizes, int n_in,
                              void* d_out, int out_size)
{
    const float* h     = (const float*)d_in[0];
    const float* norm  = (const float*)d_in[1];
    const int*   src   = (const int*)d_in[2];
    const int*   dst   = (const int*)d_in[3];
    const int*   etype = (const int*)d_in[4];
    const float* V1    = (const float*)d_in[5];
    const float* coef1 = (const float*)d_in[6];
    const float* bias1 = (const float*)d_in[7];
    const float* V2    = (const float*)d_in[8];
    const float* coef2 = (const float*)d_in[9];
    const float* bias2 = (const float*)d_in[10];
    float*       out   = (float*)d_out;

    float* h1;  cudaGetSymbolAddress((void**)&h1, g_h1);
    unsigned char *w1, *w2;
    cudaGetSymbolAddress((void**)&w1, g_w_pk1);
    cudaGetSymbolAddress((void**)&w2, g_w_pk2);

    static int smem_set = 0;
    const int GEMM_SMEM = 2048 + 1024 + 2 * TILE_BYTES;   // ~68 KB -> 2 CTAs/SM
    if (!smem_set) {
        cudaFuncSetAttribute(k_edge_gemm,
                             cudaFuncAttributeMaxDynamicSharedMemorySize, GEMM_SMEM);
        smem_set = 1;
    }

    int nh_elems  = N_NODES * HD;
    int elem_grid = (nh_elems + 255) / 256;

    // ---- prep: bucketing + packed meta (shared by both layers) + W folds
    k_zero_hist<<<1, 32>>>();
    k_hist<<<NHB, 256>>>(etype);
    k_scan_tiles<<<1, 256>>>();
    k_place<<<NHB, 256>>>(etype, src, dst, norm);
    k_fold_w2<<<2 * NR, 256>>>(V1, coef1, V2, coef2);

    // ---- Layer 1
    k_split_init<false><<<elem_grid, 256>>>(h, bias1, h1);
    k_edge_gemm<<<MAX_TILES, 256, GEMM_SMEM>>>(w1, h1);

    // ---- Layer 2
    k_split_init<true><<<elem_grid, 256>>>(h1, bias2, out);
    k_edge_gemm<<<MAX_TILES, 256, GEMM_SMEM>>>(w2, out);
}